// round 17
// baseline (speedup 1.0000x reference)
#include <cuda_runtime.h>
#include <cuda.h>
#include <cstdint>

// out = u2 + trilinear(u1, grid + u2), [B=2,160,160,160,3] fp32.
// 4 voxels per thread: u2 in via 3x LDG.128, results out via 3x STG.128
// (registers only, no staging). Warp = one x-slice, single round.
// Tile (16x4x32 + halo) filled by ONE 3D tensor-map TMA load.
// Two blocks co-reside per SM.

#define Dd 160
#define Hh 160
#define Ww 160
#define HW  (Hh * Ww)
#define DHW (Dd * HW)

#define TX 16
#define TY 4
#define TZ 32
#define XYH 3
#define ZHF 4                 // z front halo
#define SX (TX + 2 * XYH)     // 22
#define SY (TY + 2 * XYH)     // 10
#define SZ 39                 // 4 front + 32 + 3 back
#define RS (SZ * 3)           // 117 floats per tile row (odd => jittery banks spread)
#define NROW (SX * SY)        // 220
#define BUF (NROW * RS)       // 25740 floats = 102,960 B
#define TPB 512

#define MAGIC 12582912.0f     // 1.5 * 2^23
#define MAGIC_I 0x4B400000

extern __shared__ float s[];   // [BUF floats][mbarrier]

__device__ __forceinline__ void fast_floor(float v, int& i, float& f)
{
    const float fm = (v - 0.5f) + MAGIC;
    i = __float_as_int(fm) - MAGIC_I;
    f = fm - MAGIC;
}

template <bool USE_TMAP>
__global__ __launch_bounds__(TPB, 2)
void compose_kernel(const __grid_constant__ CUtensorMap tmap,
                    const float* __restrict__ w1,
                    const float* __restrict__ w2,
                    float* __restrict__ out)
{
    // blockIdx.x: xt = bx % 10 (160/TX), yt = bx / 10 (160/TY = 40)
    const int xt = blockIdx.x % 10;
    const int yt = blockIdx.x / 10;
    const int x0 = xt * TX;
    const int y0 = yt * TY;
    const int z0 = blockIdx.y * TZ;
    const int b  = blockIdx.z;

    const int t    = threadIdx.x;
    const int lane = t & 31;
    const int wrp  = t >> 5;

    const float* __restrict__ w1b = w1 + (size_t)b * (size_t)DHW * 3;

    const uint32_t mbar  = (uint32_t)__cvta_generic_to_shared(s + BUF);
    const uint32_t sbase = (uint32_t)__cvta_generic_to_shared(s);

    if (USE_TMAP) {
        if (t == 0) {
            asm volatile("mbarrier.init.shared.b64 [%0], 1;"
                         :: "r"(mbar) : "memory");
        }
        __syncthreads();
        // One 3D TMA tensor load: box (117 fl, 10, 22), OOB zero-fill
        // (zero-filled slots are provably never read by the fast path).
        if (t == 0) {
            asm volatile("mbarrier.arrive.expect_tx.shared.b64 _, [%0], %1;"
                         :: "r"(mbar), "n"(BUF * 4) : "memory");
            const int c0 = (z0 - ZHF) * 3;
            const int c1 = y0 - XYH;
            const int c2 = b * Dd + x0 - XYH;
            asm volatile(
                "cp.async.bulk.tensor.3d.shared::cta.global.tile."
                "mbarrier::complete_tx::bytes [%0], [%1, {%2, %3, %4}], [%5];"
                :: "r"(sbase), "l"(&tmap), "r"(c0), "r"(c1), "r"(c2),
                   "r"(mbar) : "memory");
        }
    } else {
        // Fallback: plain cooperative copy of valid rows (OOB rows are
        // never read by the fast path, so they may hold garbage).
        const int zlo = (z0 == 0) ? 0 : z0 - ZHF;
        const int zhi = (z0 + TZ + 3 > Ww) ? Ww : z0 + TZ + 3;
        const int n   = (zhi - zlo) * 3;             // <= 117
        const int off = (zlo - (z0 - ZHF)) * 3;
        for (int idx = t; idx < NROW * 128; idx += TPB) {
            const int r = idx >> 7;
            const int e = idx & 127;
            if (e < n) {
                const int hx = r / SY;
                const int hy = r - hx * SY;
                const int cx = x0 - XYH + hx;
                const int cy = y0 - XYH + hy;
                if ((unsigned)cx < (unsigned)Dd && (unsigned)cy < (unsigned)Hh)
                    s[r * RS + off + e] =
                        w1b[(size_t)(cx * Hh + cy) * (Ww * 3) + zlo * 3 + e];
            }
        }
    }

    // ---- Compute mapping: warp = x-slice; lane = (sy 0..3, q 0..7) ----
    const int x   = x0 + wrp;
    const int sy  = lane >> 3;           // 0..3
    const int q   = lane & 7;            // 0..7
    const int y   = y0 + sy;
    const int zb4 = z0 + q * 4;          // this thread's 4 voxels: zb4..zb4+3

    // u2 for 4 voxels: 12 floats = 3x LDG.128 (issued before the wait).
    const int f = (((b * Dd + x) * Hh + y) * Ww + zb4) * 3;
    float4 A = __ldg(reinterpret_cast<const float4*>(w2 + f));
    float4 B4 = __ldg(reinterpret_cast<const float4*>(w2 + f + 4));
    float4 C4 = __ldg(reinterpret_cast<const float4*>(w2 + f + 8));
    float u[12] = {A.x, A.y, A.z, A.w, B4.x, B4.y,
                   B4.z, B4.w, C4.x, C4.y, C4.z, C4.w};

    if (USE_TMAP) {
        uint32_t done;
        asm volatile(
            "{\n\t.reg .pred p;\n\t"
            "mbarrier.try_wait.parity.acquire.cta.shared::cta.b64 p, [%1], 0;\n\t"
            "selp.b32 %0, 1, 0, p;\n\t}"
            : "=r"(done) : "r"(mbar) : "memory");
        while (!done) {
            asm volatile(
                "{\n\t.reg .pred p;\n\t"
                "mbarrier.try_wait.parity.acquire.cta.shared::cta.b64 p, [%1], 0, 0x989680;\n\t"
                "selp.b32 %0, 1, 0, p;\n\t}"
                : "=r"(done) : "r"(mbar) : "memory");
        }
    } else {
        __syncthreads();
    }

#pragma unroll
    for (int j = 0; j < 4; ++j) {
        const int z = zb4 + j;
        const float u2x = u[3 * j + 0];
        const float u2y = u[3 * j + 1];
        const float u2z = u[3 * j + 2];

        const float lx = fminf(fmaxf((float)x + u2x, 0.0f), (float)(Dd - 1));
        const float ly = fminf(fmaxf((float)y + u2y, 0.0f), (float)(Hh - 1));
        const float lz = fminf(fmaxf((float)z + u2z, 0.0f), (float)(Ww - 1));

        int ix0, iy0, iz0;
        float fx, fy, fz;
        fast_floor(lx, ix0, fx);
        fast_floor(ly, iy0, fy);
        fast_floor(lz, iz0, fz);
        const float wx = lx - fx, wy = ly - fy, wz = lz - fz;
        const float wx0 = 1.0f - wx, wy0 = 1.0f - wy, wz0 = 1.0f - wz;

        const int sx0 = ix0 - (x0 - XYH);
        const int sy0 = iy0 - (y0 - XYH);
        const int sz0 = iz0 - (z0 - ZHF);

        float ox, oy, oz;

        const bool fast = ((unsigned)sx0 <= (unsigned)(SX - 2)) &&
                          ((unsigned)sy0 <= (unsigned)(SY - 2)) &&
                          ((unsigned)sz0 <= (unsigned)(SZ - 2));
        if (fast) {
            const int za = sz0 * 3;
            const int zb = za + 3;

            const float* p00 = s + (sx0 * SY + sy0) * RS;
            const float* p01 = p00 + RS;            // sy0+1
            const float* p10 = p00 + (SY * RS);     // sx0+1
            const float* p11 = p10 + RS;

            float acc[3];
#pragma unroll
            for (int c = 0; c < 3; ++c) {
                const float v00 = p00[za + c] * wz0 + p00[zb + c] * wz;
                const float v01 = p01[za + c] * wz0 + p01[zb + c] * wz;
                const float v10 = p10[za + c] * wz0 + p10[zb + c] * wz;
                const float v11 = p11[za + c] * wz0 + p11[zb + c] * wz;
                acc[c] = (v00 * wy0 + v01 * wy) * wx0 +
                         (v10 * wy0 + v11 * wy) * wx;
            }
            ox = acc[0]; oy = acc[1]; oz = acc[2];
        } else {
            // Rare slow path: direct global gather (exact same math).
            const int ix1 = min(ix0 + 1, Dd - 1);
            const int iy1 = min(iy0 + 1, Hh - 1);
            const int iz1 = min(iz0 + 1, Ww - 1);
            float a0 = 0.f, a1 = 0.f, a2 = 0.f;
#pragma unroll
            for (int cx = 0; cx < 2; ++cx) {
                const int   ix  = cx ? ix1 : ix0;
                const float wxx = cx ? wx : wx0;
#pragma unroll
                for (int cy = 0; cy < 2; ++cy) {
                    const int   iy  = cy ? iy1 : iy0;
                    const float wxy = wxx * (cy ? wy : wy0);
#pragma unroll
                    for (int cz = 0; cz < 2; ++cz) {
                        const int   iz  = cz ? iz1 : iz0;
                        const float wgt = wxy * (cz ? wz : wz0);
                        const int off = ((ix * Hh + iy) * Ww + iz) * 3;
                        a0 = fmaf(__ldg(w1b + off + 0), wgt, a0);
                        a1 = fmaf(__ldg(w1b + off + 1), wgt, a1);
                        a2 = fmaf(__ldg(w1b + off + 2), wgt, a2);
                    }
                }
            }
            ox = a0; oy = a1; oz = a2;
        }

        // Overwrite u2 registers in place with the result.
        u[3 * j + 0] = u2x + ox;
        u[3 * j + 1] = u2y + oy;
        u[3 * j + 2] = u2z + oz;
    }

    // 3x STG.128, streaming.
    __stcs(reinterpret_cast<float4*>(out + f),
           make_float4(u[0], u[1], u[2], u[3]));
    __stcs(reinterpret_cast<float4*>(out + f + 4),
           make_float4(u[4], u[5], u[6], u[7]));
    __stcs(reinterpret_cast<float4*>(out + f + 8),
           make_float4(u[8], u[9], u[10], u[11]));
}

typedef CUresult (*EncodeFn)(
    CUtensorMap*, CUtensorMapDataType, cuuint32_t, void*,
    const cuuint64_t*, const cuuint64_t*, const cuuint32_t*, const cuuint32_t*,
    CUtensorMapInterleave, CUtensorMapSwizzle, CUtensorMapL2promotion,
    CUtensorMapFloatOOBfill);

extern "C" void kernel_launch(void* const* d_in, const int* in_sizes, int n_in,
                              void* d_out, int out_size)
{
    const float* warp1 = (const float*)d_in[0];
    const float* warp2 = (const float*)d_in[1];
    float* out = (float*)d_out;

    const size_t smem_bytes = BUF * sizeof(float) + 16;  // 102,976

    // Build the 3D tensor map (cudart-only driver entry lookup).
    CUtensorMap tmap;
    bool have_tmap = false;
    {
        void* fn = nullptr;
        cudaDriverEntryPointQueryResult qr =
            cudaDriverEntryPointSymbolNotFound;
        cudaError_t e = cudaGetDriverEntryPoint(
            "cuTensorMapEncodeTiled", &fn, cudaEnableDefault, &qr);
        if (e == cudaSuccess && fn != nullptr &&
            qr == cudaDriverEntryPointSuccess) {
            cuuint64_t dims[3]    = {Ww * 3, Hh, (cuuint64_t)(2 * Dd)};
            cuuint64_t strides[2] = {Ww * 3 * 4, (cuuint64_t)Hh * Ww * 3 * 4};
            cuuint32_t box[3]     = {RS, SY, SX};
            cuuint32_t es[3]      = {1, 1, 1};
            EncodeFn enc = (EncodeFn)fn;
            CUresult r = enc(&tmap, CU_TENSOR_MAP_DATA_TYPE_FLOAT32, 3,
                             (void*)warp1, dims, strides, box, es,
                             CU_TENSOR_MAP_INTERLEAVE_NONE,
                             CU_TENSOR_MAP_SWIZZLE_NONE,
                             CU_TENSOR_MAP_L2_PROMOTION_L2_128B,
                             CU_TENSOR_MAP_FLOAT_OOB_FILL_NONE);
            have_tmap = (r == CUDA_SUCCESS);
        }
    }
    if (!have_tmap) {
        __builtin_memset(&tmap, 0, sizeof(tmap));  // unused by fallback
    }

    // 10 x-tiles * 40 y-tiles = 400 xy tiles; 5 z chunks; 2 batches.
    dim3 grid(400, Ww / TZ, 2);   // 4000 blocks

    if (have_tmap) {
        cudaFuncSetAttribute(compose_kernel<true>,
                             cudaFuncAttributeMaxDynamicSharedMemorySize,
                             (int)smem_bytes);
        compose_kernel<true><<<grid, TPB, smem_bytes>>>(tmap, warp1, warp2, out);
    } else {
        cudaFuncSetAttribute(compose_kernel<false>,
                             cudaFuncAttributeMaxDynamicSharedMemorySize,
                             (int)smem_bytes);
        compose_kernel<false><<<grid, TPB, smem_bytes>>>(tmap, warp1, warp2, out);
    }
}